// round 2
// baseline (speedup 1.0000x reference)
#include <cuda_runtime.h>

// Problem constants (fixed for this instance)
#define Bc 8
#define Sc 1048576
#define Cc 4
#define GW 4
#define GH 4
#define NP 16
#define PW 128
#define PH 128

#define CHUNK 2048
#define THREADS 256
#define WARPS (THREADS/32)
#define NEVENTS (Bc*Sc)                 // 8388608
#define NCHUNK (NEVENTS/CHUNK)          // 4096
#define CHUNKS_PER_BATCH (Sc/CHUNK)     // 512

// Scratch (no allocations allowed)
__device__ unsigned int g_cnt[NCHUNK * NP];
__device__ unsigned int g_base[NCHUNK * NP];
__device__ unsigned int g_total[Bc * NP];

__device__ __forceinline__ void patch_of(float x, float y, int& px, int& py) {
    px = (int)floorf(x * (1.0f / PW));
    py = (int)floorf(y * (1.0f / PH));
    px = max(0, min(GW - 1, px));
    py = max(0, min(GH - 1, py));
}

// Pass 1: per-chunk per-group counts (order-independent)
__global__ void __launch_bounds__(THREADS)
pass1_count(const float4* __restrict__ ev) {
    int chunk = blockIdx.x;
    int tid = threadIdx.x;
    int lane = tid & 31;
    __shared__ unsigned int cnt[NP];
    if (tid < NP) cnt[tid] = 0;
    __syncthreads();

    long base = (long)chunk * CHUNK;
#pragma unroll
    for (int j = 0; j < CHUNK / THREADS; j++) {
        float4 v = ev[base + j * THREADS + tid];
        int px, py;
        patch_of(v.x, v.y, px, py);
        int g = py * GW + px;
        unsigned m = __match_any_sync(0xffffffffu, g);
        if ((m & ((1u << lane) - 1u)) == 0)     // leader lane for this group
            atomicAdd(&cnt[g], (unsigned)__popc(m));
    }
    __syncthreads();
    if (tid < NP) g_cnt[chunk * NP + tid] = cnt[tid];
}

// Pass 2: exclusive scan of chunk counts per (batch,group); 1 block per group
__global__ void __launch_bounds__(CHUNKS_PER_BATCH)
pass2_scan() {
    int bg = blockIdx.x;            // 0..127
    int batch = bg >> 4;
    int g = bg & 15;
    int tid = threadIdx.x;          // 0..511

    __shared__ unsigned int s[CHUNKS_PER_BATCH];
    int chunk = batch * CHUNKS_PER_BATCH + tid;
    unsigned v = g_cnt[chunk * NP + g];
    s[tid] = v;
    __syncthreads();
#pragma unroll
    for (int off = 1; off < CHUNKS_PER_BATCH; off <<= 1) {
        unsigned t = (tid >= off) ? s[tid - off] : 0u;
        __syncthreads();
        s[tid] += t;
        __syncthreads();
    }
    g_base[chunk * NP + g] = s[tid] - v;     // exclusive prefix
    if (tid == CHUNKS_PER_BATCH - 1) g_total[bg] = s[tid];
}

// Pass 3: stable scatter, skipping chunks whose groups are all full
__global__ void __launch_bounds__(THREADS)
pass3_scatter(const float4* __restrict__ ev, float4* __restrict__ outEv,
              float* __restrict__ outMask, int L) {
    int chunk = blockIdx.x;
    int tid = threadIdx.x;
    int lane = tid & 31;
    int w = tid >> 5;

    __shared__ unsigned int run[NP];          // running base per group
    __shared__ unsigned int wc[WARPS][NP];    // per-warp per-group counts
    __shared__ int open;

    if (tid == 0) open = 0;
    __syncthreads();
    if (tid < NP) {
        unsigned b = g_base[chunk * NP + tid];
        run[tid] = b;
        if (b < (unsigned)L) atomicOr(&open, 1);
    }
    __syncthreads();
    if (!open) return;                         // ~87% of chunks exit here

    int batch = chunk / CHUNKS_PER_BATCH;
    long base = (long)chunk * CHUNK;

#pragma unroll
    for (int j = 0; j < CHUNK / THREADS; j++) {
        if (tid < WARPS * NP) ((unsigned*)wc)[tid] = 0;
        __syncthreads();

        float4 v = ev[base + j * THREADS + tid];
        int px, py;
        patch_of(v.x, v.y, px, py);
        int g = py * GW + px;

        unsigned m = __match_any_sync(0xffffffffu, g);
        unsigned lt = m & ((1u << lane) - 1u);
        unsigned r = __popc(lt);               // stable rank within warp
        if (lt == 0) wc[w][g] = (unsigned)__popc(m);
        __syncthreads();

        unsigned pre = 0;
#pragma unroll
        for (int w2 = 0; w2 < WARPS; w2++)
            if (w2 < w) pre += wc[w2][g];
        unsigned rank = run[g] + pre + r;

        if (rank < (unsigned)L) {
            long row = (long)(batch * NP + g) * L + rank;
            outEv[row] = make_float4(v.x - (float)(px * PW),
                                     v.y - (float)(py * PH), v.z, v.w);
            outMask[row] = 1.0f;
        }
        __syncthreads();

        if (tid < NP) {
            unsigned s2 = 0;
#pragma unroll
            for (int w2 = 0; w2 < WARPS; w2++) s2 += wc[w2][tid];
            run[tid] += s2;
        }
        __syncthreads();
    }
}

// Pass 4: zero only the unused tail of each group's buffer (ranks are contiguous)
__global__ void tail_fill(float4* __restrict__ outEv, float* __restrict__ outMask, int L) {
    long idx = (long)blockIdx.x * blockDim.x + threadIdx.x;
    long totalRows = (long)Bc * NP * L;
    if (idx >= totalRows) return;
    int g = (int)(idx / L);
    unsigned r = (unsigned)(idx % L);
    if (r >= g_total[g]) {
        outEv[idx] = make_float4(0.f, 0.f, 0.f, 0.f);
        outMask[idx] = 0.f;
    }
}

extern "C" void kernel_launch(void* const* d_in, const int* in_sizes, int n_in,
                              void* d_out, int out_size) {
    const float4* ev = (const float4*)d_in[0];
    float* out = (float*)d_out;

    // out layout: [B,NP,L,C] events then [B,NP,L] mask, all float32
    int L = out_size / (Bc * NP * (Cc + 1));

    float4* outEv = (float4*)out;
    float* outMask = out + (long)Bc * NP * L * Cc;

    pass1_count<<<NCHUNK, THREADS>>>(ev);
    pass2_scan<<<Bc * NP, CHUNKS_PER_BATCH>>>();
    pass3_scatter<<<NCHUNK, THREADS>>>(ev, outEv, outMask, L);

    long rows = (long)Bc * NP * L;
    int tb = (int)((rows + 255) / 256);
    tail_fill<<<tb, 256>>>(outEv, outMask, L);
}

// round 3
// speedup vs baseline: 1.5533x; 1.5533x over previous
#include <cuda_runtime.h>

#define Bc 8
#define Sc 1048576
#define Cc 4
#define GW 4
#define GH 4
#define NP 16
#define PW 128
#define PH 128

#define CHUNK 2048
#define THREADS 256
#define WARPS (THREADS/32)
#define NEVENTS (Bc*Sc)                 // 8388608
#define NCHUNK (NEVENTS/CHUNK)          // 4096
#define CHUNKS_PER_BATCH (Sc/CHUNK)     // 512
#define PRE 128                         // prefix chunks counted unconditionally

// Scratch (no allocations allowed)
__device__ unsigned int g_cnt[NCHUNK * NP];
__device__ unsigned int g_base[NCHUNK * NP];
__device__ unsigned int g_total[Bc * NP];
__device__ int g_sat[Bc];

__device__ __forceinline__ void patch_of(float x, float y, int& px, int& py) {
    px = (int)floorf(x * (1.0f / PW));
    py = (int)floorf(y * (1.0f / PH));
    px = max(0, min(GW - 1, px));
    py = max(0, min(GH - 1, py));
}

__device__ __forceinline__ void count_chunk(const float4* __restrict__ ev, int chunk) {
    int tid = threadIdx.x;
    int lane = tid & 31;
    __shared__ unsigned int cnt[NP];
    if (tid < NP) cnt[tid] = 0;
    __syncthreads();
    long base = (long)chunk * CHUNK;
#pragma unroll
    for (int j = 0; j < CHUNK / THREADS; j++) {
        float4 v = ev[base + j * THREADS + tid];
        int px, py;
        patch_of(v.x, v.y, px, py);
        int g = py * GW + px;
        unsigned m = __match_any_sync(0xffffffffu, g);
        if ((m & ((1u << lane) - 1u)) == 0)
            atomicAdd(&cnt[g], (unsigned)__popc(m));
    }
    __syncthreads();
    if (tid < NP) g_cnt[chunk * NP + tid] = cnt[tid];
}

// Pass 1a: count only the first PRE chunks of each batch (32 MB read)
__global__ void __launch_bounds__(THREADS)
pass1a_count(const float4* __restrict__ ev) {
    int b = blockIdx.x / PRE;
    int c = blockIdx.x % PRE;
    count_chunk(ev, b * CHUNKS_PER_BATCH + c);
}

// Saturation check: batch saturated iff every group got >= L events in prefix
__global__ void __launch_bounds__(256)
sat_check(int L) {
    int b = blockIdx.x;                    // 0..7
    int tid = threadIdx.x;                 // 0..255
    int g = tid & 15;
    int cs = tid >> 4;                     // 0..15
    unsigned s = 0;
    int base = b * CHUNKS_PER_BATCH;
#pragma unroll
    for (int c = cs; c < PRE; c += 16)
        s += g_cnt[(base + c) * NP + g];
    __shared__ unsigned acc[NP];
    if (tid < NP) acc[tid] = 0;
    __syncthreads();
    atomicAdd(&acc[g], s);
    __syncthreads();
    if (tid == 0) {
        int sat = 1;
#pragma unroll
        for (int g2 = 0; g2 < NP; g2++)
            if (acc[g2] < (unsigned)L) sat = 0;
        g_sat[b] = sat;
    }
}

// Pass 1b: remaining chunks — zero-fill if batch saturated, else count
__global__ void __launch_bounds__(THREADS)
pass1b_count(const float4* __restrict__ ev) {
    int b = blockIdx.x / (CHUNKS_PER_BATCH - PRE);
    int c = PRE + blockIdx.x % (CHUNKS_PER_BATCH - PRE);
    int chunk = b * CHUNKS_PER_BATCH + c;
    if (g_sat[b]) {
        if (threadIdx.x < NP) g_cnt[chunk * NP + threadIdx.x] = 0;
        return;
    }
    count_chunk(ev, chunk);
}

// Pass 2: exclusive scan of chunk counts per (batch,group); warp-shfl scan
__global__ void __launch_bounds__(CHUNKS_PER_BATCH)
pass2_scan() {
    int bg = blockIdx.x;
    int batch = bg >> 4;
    int g = bg & 15;
    int tid = threadIdx.x;
    int lane = tid & 31;
    int w = tid >> 5;                       // 0..15

    unsigned v = g_cnt[(batch * CHUNKS_PER_BATCH + tid) * NP + g];
    unsigned s = v;
#pragma unroll
    for (int off = 1; off < 32; off <<= 1) {
        unsigned t = __shfl_up_sync(0xffffffffu, s, off);
        if (lane >= off) s += t;
    }
    __shared__ unsigned wsum[16];
    if (lane == 31) wsum[w] = s;
    __syncthreads();
    if (w == 0) {
        unsigned x = (lane < 16) ? wsum[lane] : 0u;
#pragma unroll
        for (int off = 1; off < 16; off <<= 1) {
            unsigned t = __shfl_up_sync(0xffffffffu, x, off);
            if (lane >= off) x += t;
        }
        if (lane < 16) wsum[lane] = x;
    }
    __syncthreads();
    unsigned inc = s + (w > 0 ? wsum[w - 1] : 0u);
    g_base[(batch * CHUNKS_PER_BATCH + tid) * NP + g] = inc - v;
    if (tid == CHUNKS_PER_BATCH - 1) g_total[bg] = inc;
}

// Pass 3: stable scatter, skipping chunks whose groups are all full
__global__ void __launch_bounds__(THREADS)
pass3_scatter(const float4* __restrict__ ev, float4* __restrict__ outEv,
              float* __restrict__ outMask, int L) {
    int chunk = blockIdx.x;
    int tid = threadIdx.x;
    int lane = tid & 31;
    int w = tid >> 5;

    __shared__ unsigned int run[NP];
    __shared__ unsigned int wc[WARPS][NP];
    __shared__ int open;

    if (tid == 0) open = 0;
    __syncthreads();
    if (tid < NP) {
        unsigned b = g_base[chunk * NP + tid];
        run[tid] = b;
        if (b < (unsigned)L) atomicOr(&open, 1);
    }
    __syncthreads();
    if (!open) return;

    int batch = chunk / CHUNKS_PER_BATCH;
    long base = (long)chunk * CHUNK;

#pragma unroll
    for (int j = 0; j < CHUNK / THREADS; j++) {
        if (tid < WARPS * NP) ((unsigned*)wc)[tid] = 0;
        __syncthreads();

        float4 v = ev[base + j * THREADS + tid];
        int px, py;
        patch_of(v.x, v.y, px, py);
        int g = py * GW + px;

        unsigned m = __match_any_sync(0xffffffffu, g);
        unsigned lt = m & ((1u << lane) - 1u);
        unsigned r = __popc(lt);
        if (lt == 0) wc[w][g] = (unsigned)__popc(m);
        __syncthreads();

        unsigned pre = 0;
#pragma unroll
        for (int w2 = 0; w2 < WARPS; w2++)
            if (w2 < w) pre += wc[w2][g];
        unsigned rank = run[g] + pre + r;

        if (rank < (unsigned)L) {
            long row = (long)(batch * NP + g) * L + rank;
            outEv[row] = make_float4(v.x - (float)(px * PW),
                                     v.y - (float)(py * PH), v.z, v.w);
            outMask[row] = 1.0f;
        }
        __syncthreads();

        if (tid < NP) {
            unsigned s2 = 0;
#pragma unroll
            for (int w2 = 0; w2 < WARPS; w2++) s2 += wc[w2][tid];
            run[tid] += s2;
        }
        __syncthreads();
    }
}

// Pass 4: zero only unused tails; 1 block per (batch,group), usually instant exit
__global__ void __launch_bounds__(256)
tail_fill(float4* __restrict__ outEv, float* __restrict__ outMask, int L) {
    int bg = blockIdx.x;
    unsigned total = g_total[bg];
    if (total >= (unsigned)L) return;
    long rowBase = (long)bg * L;
    for (int r = (int)total + threadIdx.x; r < L; r += 256) {
        outEv[rowBase + r] = make_float4(0.f, 0.f, 0.f, 0.f);
        outMask[rowBase + r] = 0.f;
    }
}

extern "C" void kernel_launch(void* const* d_in, const int* in_sizes, int n_in,
                              void* d_out, int out_size) {
    const float4* ev = (const float4*)d_in[0];
    float* out = (float*)d_out;

    int L = out_size / (Bc * NP * (Cc + 1));
    float4* outEv = (float4*)out;
    float* outMask = out + (long)Bc * NP * L * Cc;

    pass1a_count<<<Bc * PRE, THREADS>>>(ev);
    sat_check<<<Bc, 256>>>(L);
    pass1b_count<<<Bc * (CHUNKS_PER_BATCH - PRE), THREADS>>>(ev);
    pass2_scan<<<Bc * NP, CHUNKS_PER_BATCH>>>();
    pass3_scatter<<<NCHUNK, THREADS>>>(ev, outEv, outMask, L);
    tail_fill<<<Bc * NP, 256>>>(outEv, outMask, L);
}

// round 4
// speedup vs baseline: 1.6992x; 1.0939x over previous
#include <cuda_runtime.h>

#define Bc 8
#define Sc 1048576
#define Cc 4
#define GW 4
#define GH 4
#define NP 16
#define PW 128
#define PH 128

#define CHUNK 2048
#define THREADS 256
#define WARPS (THREADS/32)
#define NEVENTS (Bc*Sc)                 // 8388608
#define NCHUNK (NEVENTS/CHUNK)          // 4096
#define CPB (Sc/CHUNK)                  // 512 chunks per batch
#define PRE 80                          // prefix chunks counted unconditionally

// Scratch (transposed layout: [group][chunk]) — no allocations allowed
__device__ unsigned g_cnt_t[NP * NCHUNK];
__device__ unsigned g_base_t[NP * NCHUNK];
__device__ unsigned g_pre[Bc * NP];     // zero-init; reset by last block each call
__device__ unsigned g_done[Bc];         // zero-init; reset by last block each call
__device__ int g_sat[Bc];               // overwritten every call

__device__ __forceinline__ void patch_of(float x, float y, int& px, int& py) {
    px = (int)floorf(x * (1.0f / PW));
    py = (int)floorf(y * (1.0f / PH));
    px = max(0, min(GW - 1, px));
    py = max(0, min(GH - 1, py));
}

__device__ __forceinline__ void count_chunk(const float4* __restrict__ ev, int chunk,
                                            unsigned* cnt) {
    int tid = threadIdx.x;
    int lane = tid & 31;
    if (tid < NP) cnt[tid] = 0;
    __syncthreads();
    long base = (long)chunk * CHUNK;
#pragma unroll
    for (int j = 0; j < CHUNK / THREADS; j++) {
        float4 v = ev[base + j * THREADS + tid];
        int px, py;
        patch_of(v.x, v.y, px, py);
        int g = py * GW + px;
        unsigned m = __match_any_sync(0xffffffffu, g);
        if ((m & ((1u << lane) - 1u)) == 0)
            atomicAdd(&cnt[g], (unsigned)__popc(m));
    }
    __syncthreads();
}

// Pass 1a: count first PRE chunks/batch + fused saturation detection
__global__ void __launch_bounds__(THREADS)
pass1a_count(const float4* __restrict__ ev, int L) {
    int b = blockIdx.x / PRE;
    int c = blockIdx.x % PRE;
    int chunk = b * CPB + c;
    int tid = threadIdx.x;
    __shared__ unsigned cnt[NP];
    count_chunk(ev, chunk, cnt);
    if (tid < NP) {
        g_cnt_t[tid * NCHUNK + chunk] = cnt[tid];
        atomicAdd(&g_pre[b * NP + tid], cnt[tid]);
        __threadfence();
    }
    __syncthreads();
    if (tid == 0) {
        unsigned d = atomicAdd(&g_done[b], 1u);
        if (d == PRE - 1) {                       // last block of this batch
            int sat = 1;
#pragma unroll
            for (int g = 0; g < NP; g++) {
                unsigned t = atomicAdd(&g_pre[b * NP + g], 0u);  // L2-coherent read
                if (t < (unsigned)L) sat = 0;
            }
            g_sat[b] = sat;
#pragma unroll
            for (int g = 0; g < NP; g++) g_pre[b * NP + g] = 0;  // reset for next replay
            g_done[b] = 0;
        }
    }
}

// Pass 1b: remaining chunks — instant exit if batch saturated (pass2 masks to 0)
__global__ void __launch_bounds__(THREADS)
pass1b_count(const float4* __restrict__ ev) {
    int b = blockIdx.x / (CPB - PRE);
    int c = PRE + blockIdx.x % (CPB - PRE);
    if (g_sat[b]) return;
    int chunk = b * CPB + c;
    __shared__ unsigned cnt[NP];
    count_chunk(ev, chunk, cnt);
    if (threadIdx.x < NP) g_cnt_t[threadIdx.x * NCHUNK + chunk] = cnt[threadIdx.x];
}

// Pass 2: coalesced per-(batch,group) scan + fused tail zero-fill
__global__ void __launch_bounds__(CPB)
pass2_scan(float4* __restrict__ outEv, float* __restrict__ outMask, int L) {
    int bg = blockIdx.x;
    int batch = bg >> 4;
    int g = bg & 15;
    int tid = threadIdx.x;
    int lane = tid & 31;
    int w = tid >> 5;                       // 0..15

    int sat = g_sat[batch];
    unsigned v = (sat && tid >= PRE) ? 0u : g_cnt_t[g * NCHUNK + batch * CPB + tid];
    unsigned s = v;
#pragma unroll
    for (int off = 1; off < 32; off <<= 1) {
        unsigned t = __shfl_up_sync(0xffffffffu, s, off);
        if (lane >= off) s += t;
    }
    __shared__ unsigned wsum[16];
    __shared__ unsigned total_s;
    if (lane == 31) wsum[w] = s;
    __syncthreads();
    if (w == 0) {
        unsigned x = (lane < 16) ? wsum[lane] : 0u;
#pragma unroll
        for (int off = 1; off < 16; off <<= 1) {
            unsigned t = __shfl_up_sync(0xffffffffu, x, off);
            if (lane >= off) x += t;
        }
        if (lane < 16) wsum[lane] = x;
    }
    __syncthreads();
    unsigned inc = s + (w > 0 ? wsum[w - 1] : 0u);
    g_base_t[g * NCHUNK + batch * CPB + tid] = inc - v;
    if (tid == CPB - 1) total_s = inc;
    __syncthreads();
    unsigned total = total_s;
    if (total < (unsigned)L) {               // tail zero-fill (usually empty)
        long rowBase = (long)bg * L;
        for (int r = (int)total + tid; r < L; r += CPB) {
            outEv[rowBase + r] = make_float4(0.f, 0.f, 0.f, 0.f);
            outMask[rowBase + r] = 0.f;
        }
    }
}

// Pass 3: stable scatter; warp-sliced, register-resident, 2 block syncs per chunk
__global__ void __launch_bounds__(THREADS)
pass3_scatter(const float4* __restrict__ ev, float4* __restrict__ outEv,
              float* __restrict__ outMask, int L) {
    int chunk = blockIdx.x;
    int tid = threadIdx.x;
    int lane = tid & 31;
    int w = tid >> 5;

    __shared__ unsigned run[NP];
    __shared__ unsigned wc[WARPS][NP];
    __shared__ unsigned upd[WARPS][NP];
    __shared__ int open;

    if (tid == 0) open = 0;
    __syncthreads();
    if (tid < NP) {
        unsigned b = g_base_t[tid * NCHUNK + chunk];
        run[tid] = b;
        if (b < (unsigned)L) atomicOr(&open, 1);
    }
    __syncthreads();
    if (!open) return;

    int batch = chunk / CPB;
    long base = (long)chunk * CHUNK + w * 256;   // contiguous 256-event warp slice
    unsigned lt = (1u << lane) - 1u;

    // prefetch entire slice into registers (full MLP)
    float4 v[8];
#pragma unroll
    for (int j = 0; j < 8; j++) v[j] = ev[base + j * 32 + lane];

    // Phase A: per-warp per-group counts; keep match masks for replay
    int g[8];
    unsigned m[8];
    unsigned wcnt = 0;                            // lane<16 holds count of group 'lane'
#pragma unroll
    for (int j = 0; j < 8; j++) {
        int px, py;
        patch_of(v[j].x, v[j].y, px, py);
        g[j] = py * GW + px;
        m[j] = __match_any_sync(0xffffffffu, g[j]);
        if (lane < NP) upd[w][lane] = 0;
        __syncwarp();
        if ((m[j] & lt) == 0) upd[w][g[j]] = (unsigned)__popc(m[j]);
        __syncwarp();
        if (lane < NP) wcnt += upd[w][lane];
    }
    if (lane < NP) wc[w][lane] = wcnt;
    __syncthreads();

    // block base per group for this warp = run[g] + counts of lower warps
    unsigned bb = 0;
    if (lane < NP) {
        bb = run[lane];
#pragma unroll
        for (int w2 = 0; w2 < WARPS; w2++)
            if (w2 < w) bb += wc[w2][lane];
    }

    // Phase B: replay from registers, compute stable ranks, scatter
    unsigned rw = 0;                              // lane<16: events of group 'lane' done in warp
#pragma unroll
    for (int j = 0; j < 8; j++) {
        unsigned r = (unsigned)__popc(m[j] & lt);
        unsigned basew = __shfl_sync(0xffffffffu, bb + rw, g[j]);
        unsigned rank = basew + r;
        if (rank < (unsigned)L) {
            int px = g[j] & 3, py = g[j] >> 2;
            long row = (long)(batch * NP + g[j]) * L + rank;
            outEv[row] = make_float4(v[j].x - (float)(px * PW),
                                     v[j].y - (float)(py * PH), v[j].z, v[j].w);
            outMask[row] = 1.0f;
        }
        if (lane < NP) upd[w][lane] = 0;
        __syncwarp();
        if ((m[j] & lt) == 0) upd[w][g[j]] = (unsigned)__popc(m[j]);
        __syncwarp();
        if (lane < NP) rw += upd[w][lane];
    }
}

extern "C" void kernel_launch(void* const* d_in, const int* in_sizes, int n_in,
                              void* d_out, int out_size) {
    const float4* ev = (const float4*)d_in[0];
    float* out = (float*)d_out;

    int L = out_size / (Bc * NP * (Cc + 1));     // 8192
    float4* outEv = (float4*)out;
    float* outMask = out + (long)Bc * NP * L * Cc;

    pass1a_count<<<Bc * PRE, THREADS>>>(ev, L);
    pass1b_count<<<Bc * (CPB - PRE), THREADS>>>(ev);
    pass2_scan<<<Bc * NP, CPB>>>(outEv, outMask, L);
    pass3_scatter<<<NCHUNK, THREADS>>>(ev, outEv, outMask, L);
}

// round 5
// speedup vs baseline: 1.8294x; 1.0766x over previous
#include <cuda_runtime.h>

#define Bc 8
#define Sc 1048576
#define Cc 4
#define GW 4
#define GH 4
#define NP 16
#define PW 128
#define PH 128

#define THREADS 256
#define NEVENTS (Bc*Sc)                 // 8388608
#define CPB 512                         // 2048-event blocks per batch (pass1 grid unit)
#define PRE 80                          // prefix blocks counted unconditionally
#define WCH 256                         // events per warp-chunk
#define NW (NEVENTS/WCH)                // 32768 warp-chunks
#define WPB (Sc/WCH)                    // 4096 warp-chunks per batch
#define PREW (PRE*8)                    // 640 prefix warp-chunks per batch

// Scratch, layout [warpchunk][group] (contiguous 64B per chunk)
__device__ unsigned g_cnt[NW * NP];     // 2 MB
__device__ unsigned g_base[NW * NP];    // 2 MB
__device__ unsigned g_pre[Bc * NP];     // zero-init; self-resetting ticket scratch
__device__ unsigned g_done[Bc];
__device__ int g_sat[Bc];
__device__ unsigned g_open[Bc];         // open warp-chunk prefix per batch

__device__ __forceinline__ int patch_of(float x, float y) {
    int px = (int)floorf(x * (1.0f / PW));
    int py = (int)floorf(y * (1.0f / PH));
    px = max(0, min(GW - 1, px));
    py = max(0, min(GH - 1, py));
    return py * GW + px;
}

// Per-warp count of its 256-event slice; returns wcnt valid in lanes<16
__device__ __forceinline__ unsigned warp_count(const float4* __restrict__ ev,
                                               long wchunk, int lane, int w,
                                               unsigned (*upd)[NP]) {
    long base = wchunk * WCH;
    float4 v[8];
#pragma unroll
    for (int j = 0; j < 8; j++) v[j] = ev[base + j * 32 + lane];
    unsigned lt = (1u << lane) - 1u;
    unsigned wcnt = 0;
#pragma unroll
    for (int j = 0; j < 8; j++) {
        int g = patch_of(v[j].x, v[j].y);
        unsigned m = __match_any_sync(0xffffffffu, g);
        if (lane < NP) upd[w][lane] = 0;
        __syncwarp();
        if ((m & lt) == 0) upd[w][g] = (unsigned)__popc(m);
        __syncwarp();
        if (lane < NP) wcnt += upd[w][lane];
        __syncwarp();
    }
    return wcnt;
}

// Pass 1a: count prefix warp-chunks + fused saturation ticket
__global__ void __launch_bounds__(THREADS)
pass1a_count(const float4* __restrict__ ev, int L) {
    int b = blockIdx.x / PRE;
    int c = blockIdx.x % PRE;
    int tid = threadIdx.x, lane = tid & 31, w = tid >> 5;
    long wchunk = (long)(b * CPB + c) * 8 + w;

    __shared__ unsigned upd[8][NP];
    __shared__ unsigned acc[NP];
    if (tid < NP) acc[tid] = 0;
    __syncthreads();

    unsigned wcnt = warp_count(ev, wchunk, lane, w, upd);
    if (lane < NP) {
        g_cnt[wchunk * NP + lane] = wcnt;
        atomicAdd(&acc[lane], wcnt);
    }
    __syncthreads();
    if (tid < NP) {
        atomicAdd(&g_pre[b * NP + tid], acc[tid]);
        __threadfence();
    }
    if (tid == 0 && c == 0) g_open[b] = 0;   // init for pass2's atomicMax
    __syncthreads();
    if (tid == 0) {
        unsigned d = atomicAdd(&g_done[b], 1u);
        if (d == PRE - 1) {
            int sat = 1;
#pragma unroll
            for (int g = 0; g < NP; g++) {
                unsigned t = atomicAdd(&g_pre[b * NP + g], 0u);
                if (t < (unsigned)L) sat = 0;
            }
            g_sat[b] = sat;
#pragma unroll
            for (int g = 0; g < NP; g++) g_pre[b * NP + g] = 0;
            g_done[b] = 0;
        }
    }
}

// Pass 1b: remaining warp-chunks — instant exit if batch saturated
__global__ void __launch_bounds__(THREADS)
pass1b_count(const float4* __restrict__ ev) {
    int b = blockIdx.x / (CPB - PRE);
    int c = PRE + blockIdx.x % (CPB - PRE);
    if (g_sat[b]) return;
    int tid = threadIdx.x, lane = tid & 31, w = tid >> 5;
    long wchunk = (long)(b * CPB + c) * 8 + w;
    __shared__ unsigned upd[8][NP];
    unsigned wcnt = warp_count(ev, wchunk, lane, w, upd);
    if (lane < NP) g_cnt[wchunk * NP + lane] = wcnt;
}

// Pass 2: per-(batch,group) scan over 4096 warp-chunks; emits bases, open
// prefix length, and tail zero-fill
__global__ void __launch_bounds__(512)
pass2_scan(float4* __restrict__ outEv, float* __restrict__ outMask, int L) {
    int bg = blockIdx.x;
    int b = bg >> 4, g = bg & 15;
    int tid = threadIdx.x, lane = tid & 31, w = tid >> 5;   // 16 warps

    int sat = g_sat[b];
    int cbase = tid * 8;                 // local warp-chunk of first element
    unsigned c8[8], ts = 0;
#pragma unroll
    for (int k = 0; k < 8; k++) {
        int lc = cbase + k;
        unsigned x = (sat && lc >= PREW) ? 0u
                   : g_cnt[((long)b * WPB + lc) * NP + g];
        c8[k] = x;
        ts += x;
    }
    // inclusive scan of per-thread sums
    unsigned s = ts;
#pragma unroll
    for (int off = 1; off < 32; off <<= 1) {
        unsigned t = __shfl_up_sync(0xffffffffu, s, off);
        if (lane >= off) s += t;
    }
    __shared__ unsigned wsum[16];
    __shared__ unsigned totsh, osh;
    if (lane == 31) wsum[w] = s;
    if (tid == 0) osh = 0;
    __syncthreads();
    if (w == 0) {
        unsigned x = (lane < 16) ? wsum[lane] : 0u;
#pragma unroll
        for (int off = 1; off < 16; off <<= 1) {
            unsigned t = __shfl_up_sync(0xffffffffu, x, off);
            if (lane >= off) x += t;
        }
        if (lane < 16) wsum[lane] = x;
    }
    __syncthreads();
    unsigned run = (s - ts) + (w > 0 ? wsum[w - 1] : 0u);   // exclusive base
    unsigned opencnt = 0;
#pragma unroll
    for (int k = 0; k < 8; k++) {
        g_base[((long)b * WPB + cbase + k) * NP + g] = run;
        if (run < (unsigned)L) opencnt++;
        run += c8[k];
    }
    if (tid == 511) totsh = run;         // group total
#pragma unroll
    for (int off = 16; off >= 1; off >>= 1)
        opencnt += __shfl_down_sync(0xffffffffu, opencnt, off);
    if (lane == 0) atomicAdd(&osh, opencnt);
    __syncthreads();
    if (tid == 0) atomicMax(&g_open[b], osh);

    unsigned total = totsh;
    if (total < (unsigned)L) {           // tail zero-fill (usually empty)
        long rowBase = (long)bg * L;
        for (int r = (int)total + tid; r < L; r += 512) {
            outEv[rowBase + r] = make_float4(0.f, 0.f, 0.f, 0.f);
            outMask[rowBase + r] = 0.f;
        }
    }
}

// Pass 3: warp-autonomous stable scatter — no block syncs, O(1) skip
__global__ void __launch_bounds__(THREADS)
pass3_scatter(const float4* __restrict__ ev, float4* __restrict__ outEv,
              float* __restrict__ outMask, int L) {
    int tid = threadIdx.x, lane = tid & 31, w = tid >> 5;
    long wchunk = (long)blockIdx.x * 8 + w;
    int b = (int)(wchunk >> 12);         // /WPB (4096)
    int local = (int)(wchunk & (WPB - 1));
    if ((unsigned)local >= g_open[b]) return;

    unsigned bb = 0;
    if (lane < NP) bb = g_base[wchunk * NP + lane];   // 64B contiguous

    long base = wchunk * WCH;
    float4 v[8];
#pragma unroll
    for (int j = 0; j < 8; j++) v[j] = ev[base + j * 32 + lane];

    __shared__ unsigned upd[8][NP];
    unsigned lt = (1u << lane) - 1u;
    unsigned rw = 0;                      // lane<16: group-'lane' events consumed
    int b16 = b * NP;
#pragma unroll
    for (int j = 0; j < 8; j++) {
        int g = patch_of(v[j].x, v[j].y);
        unsigned m = __match_any_sync(0xffffffffu, g);
        unsigned r = (unsigned)__popc(m & lt);
        if (lane < NP) upd[w][lane] = 0;
        __syncwarp();
        if ((m & lt) == 0) upd[w][g] = (unsigned)__popc(m);
        __syncwarp();
        unsigned bw = __shfl_sync(0xffffffffu, bb + rw, g);
        unsigned rank = bw + r;
        if (rank < (unsigned)L) {
            int px = g & 3, py = g >> 2;
            long row = (long)(b16 + g) * L + rank;
            outEv[row] = make_float4(v[j].x - (float)(px * PW),
                                     v[j].y - (float)(py * PH), v[j].z, v[j].w);
            outMask[row] = 1.0f;
        }
        if (lane < NP) rw += upd[w][lane];
        __syncwarp();
    }
}

extern "C" void kernel_launch(void* const* d_in, const int* in_sizes, int n_in,
                              void* d_out, int out_size) {
    const float4* ev = (const float4*)d_in[0];
    float* out = (float*)d_out;

    int L = out_size / (Bc * NP * (Cc + 1));     // 8192
    float4* outEv = (float4*)out;
    float* outMask = out + (long)Bc * NP * L * Cc;

    pass1a_count<<<Bc * PRE, THREADS>>>(ev, L);
    pass1b_count<<<Bc * (CPB - PRE), THREADS>>>(ev);
    pass2_scan<<<Bc * NP, 512>>>(outEv, outMask, L);
    pass3_scatter<<<NW / 8, THREADS>>>(ev, outEv, outMask, L);
}

// round 6
// speedup vs baseline: 1.9989x; 1.0926x over previous
#include <cuda_runtime.h>

#define Bc 8
#define Sc 1048576
#define Cc 4
#define GW 4
#define GH 4
#define NP 16
#define PW 128
#define PH 128

#define THREADS 256
#define NEVENTS (Bc*Sc)                 // 8388608
#define CPB 512                         // 2048-event blocks per batch (pass1 grid unit)
#define PRE 80                          // prefix blocks counted unconditionally
#define WCH 256                         // events per warp-chunk
#define NW (NEVENTS/WCH)                // 32768 warp-chunks
#define WPB (Sc/WCH)                    // 4096 warp-chunks per batch
#define PREW (PRE*8)                    // 640 prefix warp-chunks per batch
#define FULL 0xffffffffu

// Scratch, layout [warpchunk][group] (contiguous 64B per chunk)
__device__ unsigned g_cnt[NW * NP];     // 2 MB
__device__ unsigned g_base[NW * NP];    // 2 MB
__device__ unsigned g_pre[Bc * NP];     // zero-init; self-resetting ticket scratch
__device__ unsigned g_done[Bc];
__device__ int g_sat[Bc];
__device__ unsigned g_open[Bc];         // open warp-chunk prefix per batch

__device__ __forceinline__ int patch_of(float x, float y) {
    int px = min(GW - 1, ((int)x) >> 7);     // x,y are non-negative integer-valued
    int py = min(GH - 1, ((int)y) >> 7);
    return (py << 2) | px;
}

// group-member mask of group G from the 4 ballot planes
__device__ __forceinline__ unsigned sel_mask(int G, unsigned b0, unsigned b1,
                                             unsigned b2, unsigned b3) {
    unsigned m = (G & 1) ? b0 : ~b0;
    m &= (G & 2) ? b1 : ~b1;
    m &= (G & 4) ? b2 : ~b2;
    m &= (G & 8) ? b3 : ~b3;
    return m;
}

// Per-warp count of its 256-event slice; result valid in lanes<16 (group==lane)
__device__ __forceinline__ unsigned warp_count(const float4* __restrict__ ev,
                                               long wchunk, int lane) {
    long base = wchunk * WCH;
    float4 v[8];
#pragma unroll
    for (int j = 0; j < 8; j++) v[j] = ev[base + j * 32 + lane];
    int own = lane & 15;
    unsigned wcnt = 0;
#pragma unroll
    for (int j = 0; j < 8; j++) {
        int g = patch_of(v[j].x, v[j].y);
        unsigned b0 = __ballot_sync(FULL, g & 1);
        unsigned b1 = __ballot_sync(FULL, g & 2);
        unsigned b2 = __ballot_sync(FULL, g & 4);
        unsigned b3 = __ballot_sync(FULL, g & 8);
        wcnt += (unsigned)__popc(sel_mask(own, b0, b1, b2, b3));
    }
    return wcnt;
}

// Pass 1a: count prefix warp-chunks + fused saturation ticket
__global__ void __launch_bounds__(THREADS)
pass1a_count(const float4* __restrict__ ev, int L) {
    int b = blockIdx.x / PRE;
    int c = blockIdx.x % PRE;
    int tid = threadIdx.x, lane = tid & 31, w = tid >> 5;
    long wchunk = (long)(b * CPB + c) * 8 + w;

    __shared__ unsigned acc[NP];
    if (tid < NP) acc[tid] = 0;
    __syncthreads();

    unsigned wcnt = warp_count(ev, wchunk, lane);
    if (lane < NP) {
        g_cnt[wchunk * NP + lane] = wcnt;
        atomicAdd(&acc[lane], wcnt);
    }
    __syncthreads();
    if (tid < NP) {
        atomicAdd(&g_pre[b * NP + tid], acc[tid]);
        __threadfence();
    }
    if (tid == 0 && c == 0) g_open[b] = 0;   // init for pass2's atomicMax
    __syncthreads();
    if (tid == 0) {
        unsigned d = atomicAdd(&g_done[b], 1u);
        if (d == PRE - 1) {
            int sat = 1;
#pragma unroll
            for (int g = 0; g < NP; g++) {
                unsigned t = atomicAdd(&g_pre[b * NP + g], 0u);
                if (t < (unsigned)L) sat = 0;
            }
            g_sat[b] = sat;
#pragma unroll
            for (int g = 0; g < NP; g++) g_pre[b * NP + g] = 0;
            g_done[b] = 0;
        }
    }
}

// Pass 1b: remaining warp-chunks — instant exit if batch saturated
__global__ void __launch_bounds__(THREADS)
pass1b_count(const float4* __restrict__ ev) {
    int b = blockIdx.x / (CPB - PRE);
    int c = PRE + blockIdx.x % (CPB - PRE);
    if (g_sat[b]) return;
    int tid = threadIdx.x, lane = tid & 31, w = tid >> 5;
    long wchunk = (long)(b * CPB + c) * 8 + w;
    unsigned wcnt = warp_count(ev, wchunk, lane);
    if (lane < NP) g_cnt[wchunk * NP + lane] = wcnt;
}

// Pass 2: per-(batch,group) scan over 4096 warp-chunks; emits bases, open
// prefix length, and tail zero-fill
__global__ void __launch_bounds__(512)
pass2_scan(float4* __restrict__ outEv, float* __restrict__ outMask, int L) {
    int bg = blockIdx.x;
    int b = bg >> 4, g = bg & 15;
    int tid = threadIdx.x, lane = tid & 31, w = tid >> 5;   // 16 warps

    int sat = g_sat[b];
    int cbase = tid * 8;                 // local warp-chunk of first element
    unsigned c8[8], ts = 0;
#pragma unroll
    for (int k = 0; k < 8; k++) {
        int lc = cbase + k;
        unsigned x = (sat && lc >= PREW) ? 0u
                   : g_cnt[((long)b * WPB + lc) * NP + g];
        c8[k] = x;
        ts += x;
    }
    // inclusive scan of per-thread sums
    unsigned s = ts;
#pragma unroll
    for (int off = 1; off < 32; off <<= 1) {
        unsigned t = __shfl_up_sync(FULL, s, off);
        if (lane >= off) s += t;
    }
    __shared__ unsigned wsum[16];
    __shared__ unsigned totsh, osh;
    if (lane == 31) wsum[w] = s;
    if (tid == 0) osh = 0;
    __syncthreads();
    if (w == 0) {
        unsigned x = (lane < 16) ? wsum[lane] : 0u;
#pragma unroll
        for (int off = 1; off < 16; off <<= 1) {
            unsigned t = __shfl_up_sync(FULL, x, off);
            if (lane >= off) x += t;
        }
        if (lane < 16) wsum[lane] = x;
    }
    __syncthreads();
    unsigned run = (s - ts) + (w > 0 ? wsum[w - 1] : 0u);   // exclusive base
    unsigned opencnt = 0;
#pragma unroll
    for (int k = 0; k < 8; k++) {
        g_base[((long)b * WPB + cbase + k) * NP + g] = run;
        if (run < (unsigned)L) opencnt++;
        run += c8[k];
    }
    if (tid == 511) totsh = run;         // group total
#pragma unroll
    for (int off = 16; off >= 1; off >>= 1)
        opencnt += __shfl_down_sync(FULL, opencnt, off);
    if (lane == 0) atomicAdd(&osh, opencnt);
    __syncthreads();
    if (tid == 0) atomicMax(&g_open[b], osh);

    unsigned total = totsh;
    if (total < (unsigned)L) {           // tail zero-fill (usually empty)
        long rowBase = (long)bg * L;
        for (int r = (int)total + tid; r < L; r += 512) {
            outEv[rowBase + r] = make_float4(0.f, 0.f, 0.f, 0.f);
            outMask[rowBase + r] = 0.f;
        }
    }
}

// Pass 3: warp-autonomous stable scatter — registers only, no shared, no syncs
__global__ void __launch_bounds__(THREADS)
pass3_scatter(const float4* __restrict__ ev, float4* __restrict__ outEv,
              float* __restrict__ outMask, int L) {
    int tid = threadIdx.x, lane = tid & 31, w = tid >> 5;
    long wchunk = (long)blockIdx.x * 8 + w;
    int b = (int)(wchunk >> 12);         // /WPB (4096)
    int local = (int)(wchunk & (WPB - 1));
    if ((unsigned)local >= g_open[b]) return;

    unsigned bb = 0;
    if (lane < NP) bb = g_base[wchunk * NP + lane];   // 64B contiguous

    long base = wchunk * WCH;
    float4 v[8];
#pragma unroll
    for (int j = 0; j < 8; j++) v[j] = ev[base + j * 32 + lane];

    unsigned lt = (1u << lane) - 1u;
    int own = lane & 15;
    unsigned rw = 0;                      // lanes<16: group-'lane' events consumed
    int b16 = b * NP;
#pragma unroll
    for (int j = 0; j < 8; j++) {
        int g = patch_of(v[j].x, v[j].y);
        unsigned b0 = __ballot_sync(FULL, g & 1);
        unsigned b1 = __ballot_sync(FULL, g & 2);
        unsigned b2 = __ballot_sync(FULL, g & 4);
        unsigned b3 = __ballot_sync(FULL, g & 8);
        unsigned m = sel_mask(g, b0, b1, b2, b3);         // own-group members
        unsigned r = (unsigned)__popc(m & lt);            // stable intra-warp rank
        unsigned bw = __shfl_sync(FULL, bb + rw, g);      // group base (pre-j)
        unsigned rank = bw + r;
        if (rank < (unsigned)L) {
            int px = g & 3, py = g >> 2;
            long row = (long)(b16 + g) * L + rank;
            outEv[row] = make_float4(v[j].x - (float)(px * PW),
                                     v[j].y - (float)(py * PH), v[j].z, v[j].w);
            outMask[row] = 1.0f;
        }
        rw += (unsigned)__popc(sel_mask(own, b0, b1, b2, b3));
    }
}

extern "C" void kernel_launch(void* const* d_in, const int* in_sizes, int n_in,
                              void* d_out, int out_size) {
    const float4* ev = (const float4*)d_in[0];
    float* out = (float*)d_out;

    int L = out_size / (Bc * NP * (Cc + 1));     // 8192
    float4* outEv = (float4*)out;
    float* outMask = out + (long)Bc * NP * L * Cc;

    pass1a_count<<<Bc * PRE, THREADS>>>(ev, L);
    pass1b_count<<<Bc * (CPB - PRE), THREADS>>>(ev);
    pass2_scan<<<Bc * NP, 512>>>(outEv, outMask, L);
    pass3_scatter<<<NW / 8, THREADS>>>(ev, outEv, outMask, L);
}

// round 7
// speedup vs baseline: 2.7385x; 1.3700x over previous
#include <cuda_runtime.h>

#define Bc 8
#define Sc 1048576
#define Cc 4
#define GW 4
#define GH 4
#define NP 16
#define PW 128
#define PH 128

#define CH 2048                 // events per chunk (one block)
#define CPB (Sc/CH)             // 512 chunks per batch
#define PRE 72                  // prefix chunks counted+scattered (11-sigma sat margin)
#define FULL 0xffffffffu

#define FLAG_AGG  0x40000000u
#define FLAG_PRE  0x80000000u
#define FLAG_MASK 0xC0000000u
#define VAL_MASK  0x3FFFFFFFu

// Scratch (zero-init; reset by fallback each call for graph replay)
__device__ unsigned g_state[Bc * PRE * NP];
__device__ int g_sat[Bc];

__device__ __forceinline__ int patch_of(float x, float y) {
    int px = min(GW - 1, ((int)x) >> 7);     // coords are non-negative integer-valued
    int py = min(GH - 1, ((int)y) >> 7);
    return (py << 2) | px;
}

__device__ __forceinline__ unsigned sel_mask(int G, unsigned b0, unsigned b1,
                                             unsigned b2, unsigned b3) {
    unsigned m = (G & 1) ? b0 : ~b0;
    m &= (G & 2) ? b1 : ~b1;
    m &= (G & 4) ? b2 : ~b2;
    m &= (G & 8) ? b3 : ~b3;
    return m;
}

// Fused: count chunk -> publish AGG -> lookback -> publish PREFIX -> scatter
__global__ void __launch_bounds__(256)
fused_main(const float4* __restrict__ ev, float4* __restrict__ outEv,
           float* __restrict__ outMask, int L) {
    int b = blockIdx.x / PRE, c = blockIdx.x % PRE;
    int tid = threadIdx.x, lane = tid & 31, w = tid >> 5;

    __shared__ unsigned wc[8][NP], acc[NP], exc[NP];
    __shared__ unsigned sh[16][NP], accum_s[NP];
    __shared__ int npos_s[NP], done_s[NP], status_s, anyopen;

    if (tid < NP) acc[tid] = 0;
    __syncthreads();

    // ---- Phase A: load 256 events/warp into registers, count via ballots ----
    long base = (long)b * Sc + (long)c * CH + w * 256;
    float4 v[8];
#pragma unroll
    for (int j = 0; j < 8; j++) v[j] = ev[base + j * 32 + lane];

    int own = lane & 15;
    unsigned gpack = 0, wcnt = 0;
#pragma unroll
    for (int j = 0; j < 8; j++) {
        int g = patch_of(v[j].x, v[j].y);
        gpack |= (unsigned)g << (4 * j);
        unsigned b0 = __ballot_sync(FULL, g & 1);
        unsigned b1 = __ballot_sync(FULL, g & 2);
        unsigned b2 = __ballot_sync(FULL, g & 4);
        unsigned b3 = __ballot_sync(FULL, g & 8);
        wcnt += (unsigned)__popc(sel_mask(own, b0, b1, b2, b3));
    }
    if (lane < NP) {
        wc[w][lane] = wcnt;
        atomicAdd(&acc[lane], wcnt);
    }
    __syncthreads();

    // ---- Publish aggregate (chunk 0 publishes PREFIX directly) ----
    if (tid < NP) {
        unsigned word = acc[tid] | (c == 0 ? FLAG_PRE : FLAG_AGG);
        *(volatile unsigned*)&g_state[(b * PRE + c) * NP + tid] = word;
    }

    // ---- Decoupled lookback (windowed, 16 chunks x 16 groups per round) ----
    if (c == 0) {
        if (tid < NP) exc[tid] = 0;
        __syncthreads();
    } else {
        if (tid < NP) { npos_s[tid] = c - 1; accum_s[tid] = 0; done_s[tid] = 0; }
        __syncthreads();
        int winbase = c - 1;
        for (;;) {
            int d = tid >> 4, g = tid & 15;
            int pos = winbase - d;
            unsigned wd = 0;
            if (pos >= 0)
                wd = *(volatile unsigned*)&g_state[(b * PRE + pos) * NP + g];
            sh[d][g] = wd;
            __syncthreads();
            if (tid < NP && !done_s[tid]) {
                int np_ = npos_s[tid];
                unsigned a2 = accum_s[tid];
                while (np_ >= winbase - 15 && np_ >= 0) {
                    unsigned wd2 = sh[winbase - np_][tid];
                    unsigned f = wd2 & FLAG_MASK;
                    if (f == 0) break;                   // invalid: re-poll
                    a2 += wd2 & VAL_MASK;
                    if (f == FLAG_PRE) { done_s[tid] = 1; break; }
                    np_--;
                }
                npos_s[tid] = np_; accum_s[tid] = a2;
            }
            __syncthreads();
            if (tid == 0) {
                int alldone = 1, allbelow = 1;
#pragma unroll
                for (int g2 = 0; g2 < NP; g2++)
                    if (!done_s[g2]) {
                        alldone = 0;
                        if (npos_s[g2] >= winbase - 15) allbelow = 0;
                    }
                status_s = alldone ? 2 : (allbelow ? 1 : 0);
            }
            __syncthreads();
            if (status_s == 2) break;
            if (status_s == 1) winbase -= 16;
        }
        if (tid < NP) exc[tid] = accum_s[tid];
        __syncthreads();
        if (tid < NP)                                    // publish inclusive PREFIX
            *(volatile unsigned*)&g_state[(b * PRE + c) * NP + tid] =
                (exc[tid] + acc[tid]) | FLAG_PRE;
    }

    // ---- Saturation flag (last chunk of batch) ----
    if (c == PRE - 1 && tid == 0) {
        int sat = 1;
#pragma unroll
        for (int g2 = 0; g2 < NP; g2++)
            if (exc[g2] + acc[g2] < (unsigned)L) sat = 0;
        g_sat[b] = sat;
    }

    // ---- Early out if every group base is already >= L ----
    if (tid == 0) anyopen = 0;
    __syncthreads();
    if (tid < NP && exc[tid] < (unsigned)L) anyopen = 1;
    __syncthreads();
    if (!anyopen) return;

    // ---- Warp bases ----
    unsigned bb = 0;
    if (lane < NP) {
        bb = exc[lane];
#pragma unroll
        for (int w2 = 0; w2 < 8; w2++)
            if (w2 < w) bb += wc[w2][lane];
    }

    // ---- Phase B: scatter from registers (recompute ballots) ----
    unsigned lt = (1u << lane) - 1u;
    unsigned rw = 0;
    int b16 = b * NP;
#pragma unroll
    for (int j = 0; j < 8; j++) {
        int g = (gpack >> (4 * j)) & 15;
        unsigned b0 = __ballot_sync(FULL, g & 1);
        unsigned b1 = __ballot_sync(FULL, g & 2);
        unsigned b2 = __ballot_sync(FULL, g & 4);
        unsigned b3 = __ballot_sync(FULL, g & 8);
        unsigned m = sel_mask(g, b0, b1, b2, b3);
        unsigned r = (unsigned)__popc(m & lt);
        unsigned bw = __shfl_sync(FULL, bb + rw, g);
        unsigned rank = bw + r;
        if (rank < (unsigned)L) {
            int px = g & 3, py = g >> 2;
            long row = (long)(b16 + g) * L + rank;
            outEv[row] = make_float4(v[j].x - (float)(px * PW),
                                     v[j].y - (float)(py * PH), v[j].z, v[j].w);
            outMask[row] = 1.0f;
        }
        rw += (unsigned)__popc(sel_mask(own, b0, b1, b2, b3));
    }
}

// Fallback: correctness path if a batch didn't saturate in PRE chunks (11-sigma
// improbable, but required). Also resets g_state for the next graph replay.
__global__ void __launch_bounds__(256)
fallback(const float4* __restrict__ ev, float4* __restrict__ outEv,
         float* __restrict__ outMask, int L) {
    int b = blockIdx.x;
    int tid = threadIdx.x, lane = tid & 31, w = tid >> 5;
    __shared__ unsigned run[NP], wc[8][NP];

    if (!g_sat[b]) {
        if (tid < NP)
            run[tid] = g_state[(b * PRE + PRE - 1) * NP + tid] & VAL_MASK;
        __syncthreads();
        int own = lane & 15;
        unsigned lt = (1u << lane) - 1u;
        for (int c = PRE; c < CPB; c++) {
            long base = (long)b * Sc + (long)c * CH + w * 256;
            float4 v[8];
#pragma unroll
            for (int j = 0; j < 8; j++) v[j] = ev[base + j * 32 + lane];
            unsigned gpack = 0, wcnt = 0;
#pragma unroll
            for (int j = 0; j < 8; j++) {
                int g = patch_of(v[j].x, v[j].y);
                gpack |= (unsigned)g << (4 * j);
                unsigned b0 = __ballot_sync(FULL, g & 1);
                unsigned b1 = __ballot_sync(FULL, g & 2);
                unsigned b2 = __ballot_sync(FULL, g & 4);
                unsigned b3 = __ballot_sync(FULL, g & 8);
                wcnt += (unsigned)__popc(sel_mask(own, b0, b1, b2, b3));
            }
            if (lane < NP) wc[w][lane] = wcnt;
            __syncthreads();
            unsigned bb = 0;
            if (lane < NP) {
                bb = run[lane];
#pragma unroll
                for (int w2 = 0; w2 < 8; w2++)
                    if (w2 < w) bb += wc[w2][lane];
            }
            unsigned rw = 0;
            int b16 = b * NP;
#pragma unroll
            for (int j = 0; j < 8; j++) {
                int g = (gpack >> (4 * j)) & 15;
                unsigned b0 = __ballot_sync(FULL, g & 1);
                unsigned b1 = __ballot_sync(FULL, g & 2);
                unsigned b2 = __ballot_sync(FULL, g & 4);
                unsigned b3 = __ballot_sync(FULL, g & 8);
                unsigned m = sel_mask(g, b0, b1, b2, b3);
                unsigned r = (unsigned)__popc(m & lt);
                unsigned bw = __shfl_sync(FULL, bb + rw, g);
                unsigned rank = bw + r;
                if (rank < (unsigned)L) {
                    int px = g & 3, py = g >> 2;
                    long row = (long)(b16 + g) * L + rank;
                    outEv[row] = make_float4(v[j].x - (float)(px * PW),
                                             v[j].y - (float)(py * PH), v[j].z, v[j].w);
                    outMask[row] = 1.0f;
                }
                rw += (unsigned)__popc(sel_mask(own, b0, b1, b2, b3));
            }
            __syncthreads();
            if (tid < NP) {
                unsigned s = 0;
#pragma unroll
                for (int w2 = 0; w2 < 8; w2++) s += wc[w2][tid];
                run[tid] += s;
            }
            __syncthreads();
        }
        // tail zero-fill for any unsaturated group
        for (int g = 0; g < NP; g++) {
            unsigned t = run[g];
            if (t < (unsigned)L) {
                long rowBase = (long)(b * NP + g) * L;
                for (int r = (int)t + tid; r < L; r += 256) {
                    outEv[rowBase + r] = make_float4(0.f, 0.f, 0.f, 0.f);
                    outMask[rowBase + r] = 0.f;
                }
            }
        }
    }
    __syncthreads();
    // reset lookback state for next graph replay
    for (int i = tid; i < PRE * NP; i += 256)
        g_state[b * PRE * NP + i] = 0;
}

extern "C" void kernel_launch(void* const* d_in, const int* in_sizes, int n_in,
                              void* d_out, int out_size) {
    const float4* ev = (const float4*)d_in[0];
    float* out = (float*)d_out;

    int L = out_size / (Bc * NP * (Cc + 1));     // 8192
    float4* outEv = (float4*)out;
    float* outMask = out + (long)Bc * NP * L * Cc;

    fused_main<<<Bc * PRE, 256>>>(ev, outEv, outMask, L);
    fallback<<<Bc, 256>>>(ev, outEv, outMask, L);
}

// round 8
// speedup vs baseline: 2.7469x; 1.0031x over previous
#include <cuda_runtime.h>

#define Bc 8
#define Sc 1048576
#define Cc 4
#define GW 4
#define GH 4
#define NP 16
#define PW 128
#define PH 128

#define CH 2048                 // events per chunk (one block)
#define CPB (Sc/CH)             // 512 chunks per batch
#define PRE 72                  // prefix chunks counted+scattered (11-sigma sat margin)
#define FULL 0xffffffffu

#define FLAG_AGG  0x40000000u
#define FLAG_PRE  0x80000000u
#define FLAG_MASK 0xC0000000u
#define VAL_MASK  0x3FFFFFFFu

// Scratch (zero-init; reset by fallback each call for graph replay)
__device__ unsigned g_state[Bc * PRE * NP];
__device__ int g_sat[Bc];

__device__ __forceinline__ int patch_of(float x, float y) {
    int px = min(GW - 1, ((int)x) >> 7);     // coords are non-negative integer-valued
    int py = min(GH - 1, ((int)y) >> 7);
    return (py << 2) | px;
}

__device__ __forceinline__ unsigned sel_mask(int G, unsigned b0, unsigned b1,
                                             unsigned b2, unsigned b3) {
    unsigned m = (G & 1) ? b0 : ~b0;
    m &= (G & 2) ? b1 : ~b1;
    m &= (G & 4) ? b2 : ~b2;
    m &= (G & 8) ? b3 : ~b3;
    return m;
}

// Fused: count chunk -> publish AGG -> lookback -> publish PREFIX -> scatter
__global__ void __launch_bounds__(256)
fused_main(const float4* __restrict__ ev, float4* __restrict__ outEv,
           float* __restrict__ outMask, int L) {
    int b = blockIdx.x / PRE, c = blockIdx.x % PRE;
    int tid = threadIdx.x, lane = tid & 31, w = tid >> 5;

    __shared__ unsigned wc[8][NP], acc[NP], exc[NP];
    __shared__ unsigned sh[16][NP], accum_s[NP];
    __shared__ int npos_s[NP], done_s[NP], status_s, anyopen;

    if (tid < NP) acc[tid] = 0;
    __syncthreads();

    // ---- Phase A: load 256 events/warp into registers, count via ballots ----
    long base = (long)b * Sc + (long)c * CH + w * 256;
    float4 v[8];
#pragma unroll
    for (int j = 0; j < 8; j++) v[j] = ev[base + j * 32 + lane];

    int own = lane & 15;
    unsigned gpack = 0, wcnt = 0;
#pragma unroll
    for (int j = 0; j < 8; j++) {
        int g = patch_of(v[j].x, v[j].y);
        gpack |= (unsigned)g << (4 * j);
        unsigned b0 = __ballot_sync(FULL, g & 1);
        unsigned b1 = __ballot_sync(FULL, g & 2);
        unsigned b2 = __ballot_sync(FULL, g & 4);
        unsigned b3 = __ballot_sync(FULL, g & 8);
        wcnt += (unsigned)__popc(sel_mask(own, b0, b1, b2, b3));
    }
    if (lane < NP) {
        wc[w][lane] = wcnt;
        atomicAdd(&acc[lane], wcnt);
    }
    __syncthreads();

    // ---- Publish aggregate (chunk 0 publishes PREFIX directly) ----
    if (tid < NP) {
        unsigned word = acc[tid] | (c == 0 ? FLAG_PRE : FLAG_AGG);
        *(volatile unsigned*)&g_state[(b * PRE + c) * NP + tid] = word;
    }

    // ---- Decoupled lookback (windowed, 16 chunks x 16 groups per round) ----
    if (c == 0) {
        if (tid < NP) exc[tid] = 0;
        __syncthreads();
    } else {
        if (tid < NP) { npos_s[tid] = c - 1; accum_s[tid] = 0; done_s[tid] = 0; }
        __syncthreads();
        int winbase = c - 1;
        for (;;) {
            int d = tid >> 4, g = tid & 15;
            int pos = winbase - d;
            unsigned wd = 0;
            if (pos >= 0)
                wd = *(volatile unsigned*)&g_state[(b * PRE + pos) * NP + g];
            sh[d][g] = wd;
            __syncthreads();
            if (tid < NP && !done_s[tid]) {
                int np_ = npos_s[tid];
                unsigned a2 = accum_s[tid];
                while (np_ >= winbase - 15 && np_ >= 0) {
                    unsigned wd2 = sh[winbase - np_][tid];
                    unsigned f = wd2 & FLAG_MASK;
                    if (f == 0) break;                   // invalid: re-poll
                    a2 += wd2 & VAL_MASK;
                    if (f == FLAG_PRE) { done_s[tid] = 1; break; }
                    np_--;
                }
                npos_s[tid] = np_; accum_s[tid] = a2;
            }
            __syncthreads();
            if (tid == 0) {
                int alldone = 1, allbelow = 1;
#pragma unroll
                for (int g2 = 0; g2 < NP; g2++)
                    if (!done_s[g2]) {
                        alldone = 0;
                        if (npos_s[g2] >= winbase - 15) allbelow = 0;
                    }
                status_s = alldone ? 2 : (allbelow ? 1 : 0);
            }
            __syncthreads();
            if (status_s == 2) break;
            if (status_s == 1) winbase -= 16;
        }
        if (tid < NP) exc[tid] = accum_s[tid];
        __syncthreads();
        if (tid < NP)                                    // publish inclusive PREFIX
            *(volatile unsigned*)&g_state[(b * PRE + c) * NP + tid] =
                (exc[tid] + acc[tid]) | FLAG_PRE;
    }

    // ---- Saturation flag (last chunk of batch) ----
    if (c == PRE - 1 && tid == 0) {
        int sat = 1;
#pragma unroll
        for (int g2 = 0; g2 < NP; g2++)
            if (exc[g2] + acc[g2] < (unsigned)L) sat = 0;
        g_sat[b] = sat;
    }

    // ---- Early out if every group base is already >= L ----
    if (tid == 0) anyopen = 0;
    __syncthreads();
    if (tid < NP && exc[tid] < (unsigned)L) anyopen = 1;
    __syncthreads();
    if (!anyopen) return;

    // ---- Warp bases ----
    unsigned bb = 0;
    if (lane < NP) {
        bb = exc[lane];
#pragma unroll
        for (int w2 = 0; w2 < 8; w2++)
            if (w2 < w) bb += wc[w2][lane];
    }

    // ---- Phase B: scatter from registers (recompute ballots) ----
    unsigned lt = (1u << lane) - 1u;
    unsigned rw = 0;
    int b16 = b * NP;
#pragma unroll
    for (int j = 0; j < 8; j++) {
        int g = (gpack >> (4 * j)) & 15;
        unsigned b0 = __ballot_sync(FULL, g & 1);
        unsigned b1 = __ballot_sync(FULL, g & 2);
        unsigned b2 = __ballot_sync(FULL, g & 4);
        unsigned b3 = __ballot_sync(FULL, g & 8);
        unsigned m = sel_mask(g, b0, b1, b2, b3);
        unsigned r = (unsigned)__popc(m & lt);
        unsigned bw = __shfl_sync(FULL, bb + rw, g);
        unsigned rank = bw + r;
        if (rank < (unsigned)L) {
            int px = g & 3, py = g >> 2;
            long row = (long)(b16 + g) * L + rank;
            outEv[row] = make_float4(v[j].x - (float)(px * PW),
                                     v[j].y - (float)(py * PH), v[j].z, v[j].w);
            outMask[row] = 1.0f;
        }
        rw += (unsigned)__popc(sel_mask(own, b0, b1, b2, b3));
    }
}

// Fallback: correctness path if a batch didn't saturate in PRE chunks (11-sigma
// improbable, but required). Also resets g_state for the next graph replay.
__global__ void __launch_bounds__(256)
fallback(const float4* __restrict__ ev, float4* __restrict__ outEv,
         float* __restrict__ outMask, int L) {
    int b = blockIdx.x;
    int tid = threadIdx.x, lane = tid & 31, w = tid >> 5;
    __shared__ unsigned run[NP], wc[8][NP];

    if (!g_sat[b]) {
        if (tid < NP)
            run[tid] = g_state[(b * PRE + PRE - 1) * NP + tid] & VAL_MASK;
        __syncthreads();
        int own = lane & 15;
        unsigned lt = (1u << lane) - 1u;
        for (int c = PRE; c < CPB; c++) {
            long base = (long)b * Sc + (long)c * CH + w * 256;
            float4 v[8];
#pragma unroll
            for (int j = 0; j < 8; j++) v[j] = ev[base + j * 32 + lane];
            unsigned gpack = 0, wcnt = 0;
#pragma unroll
            for (int j = 0; j < 8; j++) {
                int g = patch_of(v[j].x, v[j].y);
                gpack |= (unsigned)g << (4 * j);
                unsigned b0 = __ballot_sync(FULL, g & 1);
                unsigned b1 = __ballot_sync(FULL, g & 2);
                unsigned b2 = __ballot_sync(FULL, g & 4);
                unsigned b3 = __ballot_sync(FULL, g & 8);
                wcnt += (unsigned)__popc(sel_mask(own, b0, b1, b2, b3));
            }
            if (lane < NP) wc[w][lane] = wcnt;
            __syncthreads();
            unsigned bb = 0;
            if (lane < NP) {
                bb = run[lane];
#pragma unroll
                for (int w2 = 0; w2 < 8; w2++)
                    if (w2 < w) bb += wc[w2][lane];
            }
            unsigned rw = 0;
            int b16 = b * NP;
#pragma unroll
            for (int j = 0; j < 8; j++) {
                int g = (gpack >> (4 * j)) & 15;
                unsigned b0 = __ballot_sync(FULL, g & 1);
                unsigned b1 = __ballot_sync(FULL, g & 2);
                unsigned b2 = __ballot_sync(FULL, g & 4);
                unsigned b3 = __ballot_sync(FULL, g & 8);
                unsigned m = sel_mask(g, b0, b1, b2, b3);
                unsigned r = (unsigned)__popc(m & lt);
                unsigned bw = __shfl_sync(FULL, bb + rw, g);
                unsigned rank = bw + r;
                if (rank < (unsigned)L) {
                    int px = g & 3, py = g >> 2;
                    long row = (long)(b16 + g) * L + rank;
                    outEv[row] = make_float4(v[j].x - (float)(px * PW),
                                             v[j].y - (float)(py * PH), v[j].z, v[j].w);
                    outMask[row] = 1.0f;
                }
                rw += (unsigned)__popc(sel_mask(own, b0, b1, b2, b3));
            }
            __syncthreads();
            if (tid < NP) {
                unsigned s = 0;
#pragma unroll
                for (int w2 = 0; w2 < 8; w2++) s += wc[w2][tid];
                run[tid] += s;
            }
            __syncthreads();
        }
        // tail zero-fill for any unsaturated group
        for (int g = 0; g < NP; g++) {
            unsigned t = run[g];
            if (t < (unsigned)L) {
                long rowBase = (long)(b * NP + g) * L;
                for (int r = (int)t + tid; r < L; r += 256) {
                    outEv[rowBase + r] = make_float4(0.f, 0.f, 0.f, 0.f);
                    outMask[rowBase + r] = 0.f;
                }
            }
        }
    }
    __syncthreads();
    // reset lookback state for next graph replay
    for (int i = tid; i < PRE * NP; i += 256)
        g_state[b * PRE * NP + i] = 0;
}

extern "C" void kernel_launch(void* const* d_in, const int* in_sizes, int n_in,
                              void* d_out, int out_size) {
    const float4* ev = (const float4*)d_in[0];
    float* out = (float*)d_out;

    int L = out_size / (Bc * NP * (Cc + 1));     // 8192
    float4* outEv = (float4*)out;
    float* outMask = out + (long)Bc * NP * L * Cc;

    fused_main<<<Bc * PRE, 256>>>(ev, outEv, outMask, L);
    fallback<<<Bc, 256>>>(ev, outEv, outMask, L);
}